// round 1
// baseline (speedup 1.0000x reference)
#include <cuda_runtime.h>

#define CDIM 256
#define KNUM 1024
#define NPIX 131072
#define PXB  128
#define KCH  64
#define NBLK (NPIX / PXB)          // 1024 blocks
#define XQ_ELEMS 33554432          // 32*256*64*64
#define SMEM_BYTES ((CDIM*PXB + CDIM*KCH + PXB + KCH) * 4)  // 197376

__device__ float g_ee[KNUM];
__device__ float g_embT[KNUM * CDIM];   // [c][k]
__device__ int   g_idx[NPIX];
__device__ float g_losspart[NBLK];

__device__ __forceinline__ unsigned long long dup2(float v) {
    unsigned u = __float_as_uint(v);
    unsigned long long r;
    asm("mov.b64 %0, {%1, %1};" : "=l"(r) : "r"(u));
    return r;
}
__device__ __forceinline__ void fma2(unsigned long long &d, unsigned long long a, unsigned long long b) {
    asm("fma.rn.f32x2 %0, %1, %2, %0;" : "+l"(d) : "l"(a), "l"(b));
}

// Transpose emb -> embT, and compute per-code squared norms.
__global__ void prep_kernel(const float* __restrict__ emb) {
    int t = blockIdx.x * blockDim.x + threadIdx.x;
    if (t < KNUM * CDIM) {
        int c = t >> 10;       // embT index: c*1024 + k
        int k = t & 1023;
        g_embT[t] = emb[k * CDIM + c];
    }
    if (t < KNUM) {
        const float* e = emb + (size_t)t * CDIM;
        float s = 0.f;
        for (int c = 0; c < CDIM; ++c)
            s = __fadd_rn(s, __fmul_rn(e[c], e[c]));
        g_ee[t] = s;
    }
}

// Main: per block 128 pixels x 1024 codes; fp32 dots via packed f32x2 FMA.
__global__ __launch_bounds__(256, 1)
void vq_main(const float* __restrict__ x) {
    extern __shared__ float sm[];
    float* xs  = sm;                       // [CDIM][PXB]
    float* es  = xs + CDIM * PXB;          // [CDIM][KCH] (transposed chunk)
    float* xxs = es + CDIM * KCH;          // [PXB] row squared norms
    float* ees = xxs + PXB;                // [KCH] code squared norms

    const int tid = threadIdx.x;
    const int p0  = blockIdx.x * PXB;
    const int bimg = p0 >> 12;             // 4096 pixels per batch image
    const int hw0  = p0 & 4095;
    const float* xb = x + ((size_t)bimg * CDIM) * 4096 + hw0;

    // Stage x tile: [c][px], coalesced float4 loads.
    for (int v = tid; v < (CDIM * PXB) / 4; v += 256) {
        int c = v >> 5;                    // 32 float4 per 128-px row
        int j = (v & 31) << 2;
        *(float4*)(xs + c * PXB + j) = *(const float4*)(xb + (size_t)c * 4096 + j);
    }
    __syncthreads();

    // Per-pixel ||x||^2 (mul then add, mimicking xf*xf followed by sum)
    if (tid < PXB) {
        float s = 0.f;
        #pragma unroll 8
        for (int c = 0; c < CDIM; ++c) {
            float v = xs[c * PXB + tid];
            s = __fadd_rn(s, __fmul_rn(v, v));
        }
        xxs[tid] = s;
    }

    const int tx = tid & 15;               // 16 code-groups (4 codes each)
    const int ty = tid >> 4;               // 16 pixel-groups (8 px each)
    const int pxbase = ty * 8;

    float bestv[8]; int bestk[8];
    #pragma unroll
    for (int p = 0; p < 8; ++p) { bestv[p] = __int_as_float(0x7f800000); bestk[p] = 0; }

    for (int k0 = 0; k0 < KNUM; k0 += KCH) {
        __syncthreads();  // previous chunk compute done before overwrite
        // Stage e chunk transposed: es[c][kk], coalesced from g_embT
        for (int v = tid; v < (CDIM * KCH) / 4; v += 256) {
            int c = v >> 4;                // 16 float4 per 64-code row
            int j = (v & 15) << 2;
            *(float4*)(es + c * KCH + j) = *(const float4*)(g_embT + c * KNUM + k0 + j);
        }
        if (tid < KCH) ees[tid] = g_ee[k0 + tid];
        __syncthreads();

        unsigned long long acc[8][2];
        #pragma unroll
        for (int p = 0; p < 8; ++p) { acc[p][0] = 0ull; acc[p][1] = 0ull; }

        #pragma unroll 4
        for (int c = 0; c < CDIM; ++c) {
            const float* xr = xs + c * PXB + pxbase;
            float4 xa = *(const float4*)xr;
            float4 xc = *(const float4*)(xr + 4);
            const unsigned long long* er =
                (const unsigned long long*)(es + c * KCH + (tx << 2));
            unsigned long long e01 = er[0];
            unsigned long long e23 = er[1];
            unsigned long long d0 = dup2(xa.x), d1 = dup2(xa.y);
            unsigned long long d2 = dup2(xa.z), d3 = dup2(xa.w);
            unsigned long long d4 = dup2(xc.x), d5 = dup2(xc.y);
            unsigned long long d6 = dup2(xc.z), d7 = dup2(xc.w);
            fma2(acc[0][0], d0, e01); fma2(acc[0][1], d0, e23);
            fma2(acc[1][0], d1, e01); fma2(acc[1][1], d1, e23);
            fma2(acc[2][0], d2, e01); fma2(acc[2][1], d2, e23);
            fma2(acc[3][0], d3, e01); fma2(acc[3][1], d3, e23);
            fma2(acc[4][0], d4, e01); fma2(acc[4][1], d4, e23);
            fma2(acc[5][0], d5, e01); fma2(acc[5][1], d5, e23);
            fma2(acc[6][0], d6, e01); fma2(acc[6][1], d6, e23);
            fma2(acc[7][0], d7, e01); fma2(acc[7][1], d7, e23);
        }

        // d = fl( fl(||x||^2 + ||e||^2) - 2*dot ), mimicking (a+b) - 2c in jax
        #pragma unroll
        for (int p = 0; p < 8; ++p) {
            float xxv = xxs[pxbase + p];
            #pragma unroll
            for (int q = 0; q < 4; ++q) {
                unsigned long long a = acc[p][q >> 1];
                float dot = __uint_as_float(
                    (q & 1) ? (unsigned)(a >> 32) : (unsigned)(a & 0xffffffffu));
                int kk = (tx << 2) + q;
                float t = __fadd_rn(xxv, ees[kk]);
                float d = __fmaf_rn(-2.f, dot, t);
                if (d < bestv[p]) { bestv[p] = d; bestk[p] = k0 + kk; }
            }
        }
    }
    __syncthreads();

    // Cross-tx argmin reduce per pixel (tie -> lowest k, matching jnp.argmin)
    float* rv = es;                         // [PXB][16]
    int*   rk = (int*)(es + PXB * 16);      // [PXB][16]
    #pragma unroll
    for (int p = 0; p < 8; ++p) {
        rv[(pxbase + p) * 16 + tx] = bestv[p];
        rk[(pxbase + p) * 16 + tx] = bestk[p];
    }
    __syncthreads();
    if (tid < PXB) {
        float bv = rv[tid * 16]; int bk = rk[tid * 16];
        #pragma unroll
        for (int t = 1; t < 16; ++t) {
            float v = rv[tid * 16 + t]; int kx = rk[tid * 16 + t];
            if (v < bv || (v == bv && kx < bk)) { bv = v; bk = kx; }
        }
        g_idx[p0 + tid] = bk;
        xxs[tid] = bv;                      // d_min = ||x - e_idx||^2 for loss
    }
    __syncthreads();
    for (int s = 64; s > 0; s >>= 1) {
        if (tid < s) xxs[tid] += xxs[tid + s];
        __syncthreads();
    }
    if (tid == 0) g_losspart[blockIdx.x] = xxs[0];
}

// Write x_q_out (straight-through value == emb[idx]) in [B,C,H,W] layout.
__global__ void gather_kernel(float* __restrict__ out, int out_size) {
    int t = blockIdx.x * blockDim.x + threadIdx.x;
    int o = t << 2;                         // 4 outputs per thread, exact coverage
    int bq = o >> 20;                       // CDIM*4096 = 1048576 per image
    int r  = o & 1048575;
    int c  = r >> 12;
    int hw = r & 4095;
    int n  = (bq << 12) + hw;
    const float* row = g_embT + c * KNUM;   // 4KB row, L1-resident
    float4 v;
    v.x = row[g_idx[n + 0]];
    v.y = row[g_idx[n + 1]];
    v.z = row[g_idx[n + 2]];
    v.w = row[g_idx[n + 3]];
    if (o + 3 < out_size) *(float4*)(out + o) = v;
}

// idx (as float) + scalar loss
__global__ void tail_kernel(float* __restrict__ out, int out_size) {
    int n = blockIdx.x * blockDim.x + threadIdx.x;
    if (n < NPIX) {
        int o = XQ_ELEMS + n;
        if (o < out_size) out[o] = (float)g_idx[n];
    }
    if (n == 0) {
        float s = 0.f;
        for (int i = 0; i < NBLK; ++i) s += g_losspart[i];
        int o = XQ_ELEMS + NPIX;
        // loss = (1 + BETA) * mean(||x - e_idx||^2 elementwise) ; 1.25/2^25 exact
        if (o < out_size) out[o] = s * (1.25f / 33554432.f);
    }
}

extern "C" void kernel_launch(void* const* d_in, const int* in_sizes, int n_in,
                              void* d_out, int out_size) {
    const float* x   = (const float*)d_in[0];
    const float* emb = (const float*)d_in[1];
    float* out = (float*)d_out;

    cudaFuncSetAttribute(vq_main, cudaFuncAttributeMaxDynamicSharedMemorySize, SMEM_BYTES);

    prep_kernel<<<(KNUM * CDIM) / 256, 256>>>(emb);
    vq_main<<<NBLK, 256, SMEM_BYTES>>>(x);
    gather_kernel<<<XQ_ELEMS / 4 / 256, 256>>>(out, out_size);
    tail_kernel<<<(NPIX + 255) / 256, 256>>>(out, out_size);
}

// round 2
// speedup vs baseline: 1.0013x; 1.0013x over previous
#include <cuda_runtime.h>

#define CDIM 256
#define KNUM 1024
#define NPIX 131072
#define PXB  128
#define KCH  64
#define NBLK (NPIX / PXB)          // 1024 blocks
#define XQ_ELEMS 33554432          // 32*256*64*64
#define SMEM_BYTES ((CDIM*PXB + CDIM*KCH + PXB + KCH) * 4)  // 197376

__device__ float g_ee[KNUM];
__device__ float g_embT[KNUM * CDIM];   // [c][k]
__device__ int   g_idx[NPIX];
__device__ float g_losspart[NBLK];

__device__ __forceinline__ unsigned long long dup2(float v) {
    unsigned u = __float_as_uint(v);
    unsigned long long r;
    asm("mov.b64 %0, {%1, %1};" : "=l"(r) : "r"(u));
    return r;
}
__device__ __forceinline__ void fma2(unsigned long long &d, unsigned long long a, unsigned long long b) {
    asm("fma.rn.f32x2 %0, %1, %2, %0;" : "+l"(d) : "l"(a), "l"(b));
}

// Transpose emb -> embT, and compute per-code squared norms.
__global__ void prep_kernel(const float* __restrict__ emb) {
    int t = blockIdx.x * blockDim.x + threadIdx.x;
    if (t < KNUM * CDIM) {
        int c = t >> 10;       // embT index: c*1024 + k
        int k = t & 1023;
        g_embT[t] = emb[k * CDIM + c];
    }
    if (t < KNUM) {
        const float* e = emb + (size_t)t * CDIM;
        float s = 0.f;
        for (int c = 0; c < CDIM; ++c)
            s = __fadd_rn(s, __fmul_rn(e[c], e[c]));
        g_ee[t] = s;
    }
}

// Main: per block 128 pixels x 1024 codes; fp32 dots via packed f32x2 FMA.
__global__ __launch_bounds__(256, 1)
void vq_main(const float* __restrict__ x) {
    extern __shared__ float sm[];
    float* xs  = sm;                       // [CDIM][PXB]
    float* es  = xs + CDIM * PXB;          // [CDIM][KCH] (transposed chunk)
    float* xxs = es + CDIM * KCH;          // [PXB] row squared norms
    float* ees = xxs + PXB;                // [KCH] code squared norms

    const int tid = threadIdx.x;
    const int p0  = blockIdx.x * PXB;
    const int bimg = p0 >> 12;             // 4096 pixels per batch image
    const int hw0  = p0 & 4095;
    const float* xb = x + ((size_t)bimg * CDIM) * 4096 + hw0;

    // Stage x tile: [c][px], coalesced float4 loads.
    for (int v = tid; v < (CDIM * PXB) / 4; v += 256) {
        int c = v >> 5;                    // 32 float4 per 128-px row
        int j = (v & 31) << 2;
        *(float4*)(xs + c * PXB + j) = *(const float4*)(xb + (size_t)c * 4096 + j);
    }
    __syncthreads();

    // Per-pixel ||x||^2 (mul then add, mimicking xf*xf followed by sum)
    if (tid < PXB) {
        float s = 0.f;
        #pragma unroll 8
        for (int c = 0; c < CDIM; ++c) {
            float v = xs[c * PXB + tid];
            s = __fadd_rn(s, __fmul_rn(v, v));
        }
        xxs[tid] = s;
    }

    const int tx = tid & 15;               // 16 code-groups (4 codes each)
    const int ty = tid >> 4;               // 16 pixel-groups (8 px each)
    const int pxbase = ty * 8;

    float bestv[8]; int bestk[8];
    #pragma unroll
    for (int p = 0; p < 8; ++p) { bestv[p] = __int_as_float(0x7f800000); bestk[p] = 0; }

    for (int k0 = 0; k0 < KNUM; k0 += KCH) {
        __syncthreads();  // previous chunk compute done before overwrite
        // Stage e chunk transposed: es[c][kk], coalesced from g_embT
        for (int v = tid; v < (CDIM * KCH) / 4; v += 256) {
            int c = v >> 4;                // 16 float4 per 64-code row
            int j = (v & 15) << 2;
            *(float4*)(es + c * KCH + j) = *(const float4*)(g_embT + c * KNUM + k0 + j);
        }
        if (tid < KCH) ees[tid] = g_ee[k0 + tid];
        __syncthreads();

        unsigned long long acc[8][2];
        #pragma unroll
        for (int p = 0; p < 8; ++p) { acc[p][0] = 0ull; acc[p][1] = 0ull; }

        #pragma unroll 4
        for (int c = 0; c < CDIM; ++c) {
            const float* xr = xs + c * PXB + pxbase;
            float4 xa = *(const float4*)xr;
            float4 xc = *(const float4*)(xr + 4);
            const unsigned long long* er =
                (const unsigned long long*)(es + c * KCH + (tx << 2));
            unsigned long long e01 = er[0];
            unsigned long long e23 = er[1];
            unsigned long long d0 = dup2(xa.x), d1 = dup2(xa.y);
            unsigned long long d2 = dup2(xa.z), d3 = dup2(xa.w);
            unsigned long long d4 = dup2(xc.x), d5 = dup2(xc.y);
            unsigned long long d6 = dup2(xc.z), d7 = dup2(xc.w);
            fma2(acc[0][0], d0, e01); fma2(acc[0][1], d0, e23);
            fma2(acc[1][0], d1, e01); fma2(acc[1][1], d1, e23);
            fma2(acc[2][0], d2, e01); fma2(acc[2][1], d2, e23);
            fma2(acc[3][0], d3, e01); fma2(acc[3][1], d3, e23);
            fma2(acc[4][0], d4, e01); fma2(acc[4][1], d4, e23);
            fma2(acc[5][0], d5, e01); fma2(acc[5][1], d5, e23);
            fma2(acc[6][0], d6, e01); fma2(acc[6][1], d6, e23);
            fma2(acc[7][0], d7, e01); fma2(acc[7][1], d7, e23);
        }

        // d = fl( fl(||x||^2 + ||e||^2) - 2*dot ), mimicking (a+b) - 2c in jax
        #pragma unroll
        for (int p = 0; p < 8; ++p) {
            float xxv = xxs[pxbase + p];
            #pragma unroll
            for (int q = 0; q < 4; ++q) {
                unsigned long long a = acc[p][q >> 1];
                float dot = __uint_as_float(
                    (q & 1) ? (unsigned)(a >> 32) : (unsigned)(a & 0xffffffffu));
                int kk = (tx << 2) + q;
                float t = __fadd_rn(xxv, ees[kk]);
                float d = __fmaf_rn(-2.f, dot, t);
                if (d < bestv[p]) { bestv[p] = d; bestk[p] = k0 + kk; }
            }
        }
    }
    __syncthreads();

    // Cross-tx argmin reduce per pixel (tie -> lowest k, matching jnp.argmin)
    float* rv = es;                         // [PXB][16]
    int*   rk = (int*)(es + PXB * 16);      // [PXB][16]
    #pragma unroll
    for (int p = 0; p < 8; ++p) {
        rv[(pxbase + p) * 16 + tx] = bestv[p];
        rk[(pxbase + p) * 16 + tx] = bestk[p];
    }
    __syncthreads();
    if (tid < PXB) {
        float bv = rv[tid * 16]; int bk = rk[tid * 16];
        #pragma unroll
        for (int t = 1; t < 16; ++t) {
            float v = rv[tid * 16 + t]; int kx = rk[tid * 16 + t];
            if (v < bv || (v == bv && kx < bk)) { bv = v; bk = kx; }
        }
        g_idx[p0 + tid] = bk;
        xxs[tid] = bv;                      // d_min = ||x - e_idx||^2 for loss
    }
    __syncthreads();
    for (int s = 64; s > 0; s >>= 1) {
        if (tid < s) xxs[tid] += xxs[tid + s];
        __syncthreads();
    }
    if (tid == 0) g_losspart[blockIdx.x] = xxs[0];
}

// Write x_q_out (straight-through value == emb[idx]) in [B,C,H,W] layout.
__global__ void gather_kernel(float* __restrict__ out, int out_size) {
    int t = blockIdx.x * blockDim.x + threadIdx.x;
    int o = t << 2;                         // 4 outputs per thread, exact coverage
    int bq = o >> 20;                       // CDIM*4096 = 1048576 per image
    int r  = o & 1048575;
    int c  = r >> 12;
    int hw = r & 4095;
    int n  = (bq << 12) + hw;
    const float* row = g_embT + c * KNUM;   // 4KB row, L1-resident
    float4 v;
    v.x = row[g_idx[n + 0]];
    v.y = row[g_idx[n + 1]];
    v.z = row[g_idx[n + 2]];
    v.w = row[g_idx[n + 3]];
    if (o + 3 < out_size) *(float4*)(out + o) = v;
}

// idx (as float) + scalar loss
__global__ void tail_kernel(float* __restrict__ out, int out_size) {
    int n = blockIdx.x * blockDim.x + threadIdx.x;
    if (n < NPIX) {
        int o = XQ_ELEMS + n;
        if (o < out_size) out[o] = (float)g_idx[n];
    }
    if (n == 0) {
        float s = 0.f;
        for (int i = 0; i < NBLK; ++i) s += g_losspart[i];
        int o = XQ_ELEMS + NPIX;
        // loss = (1 + BETA) * mean(||x - e_idx||^2 elementwise) ; 1.25/2^25 exact
        if (o < out_size) out[o] = s * (1.25f / 33554432.f);
    }
}

extern "C" void kernel_launch(void* const* d_in, const int* in_sizes, int n_in,
                              void* d_out, int out_size) {
    const float* x   = (const float*)d_in[0];
    const float* emb = (const float*)d_in[1];
    float* out = (float*)d_out;

    cudaFuncSetAttribute(vq_main, cudaFuncAttributeMaxDynamicSharedMemorySize, SMEM_BYTES);

    prep_kernel<<<(KNUM * CDIM) / 256, 256>>>(emb);
    vq_main<<<NBLK, 256, SMEM_BYTES>>>(x);
    gather_kernel<<<XQ_ELEMS / 4 / 256, 256>>>(out, out_size);
    tail_kernel<<<(NPIX + 255) / 256, 256>>>(out, out_size);
}

// round 7
// speedup vs baseline: 1.2258x; 1.2241x over previous
#include <cuda_runtime.h>
#include <cuda_bf16.h>
#include <cstdint>

#define CDIM 256
#define KNUM 1024
#define NPIX 131072
#define PXB  128
#define CAPS 12
#define DELTA 0.004f
#define XQ_ELEMS 33554432
#define NBLK (NPIX / PXB)

// smem byte offsets
#define OFF_XS   0        // 131072 : x fp32 [c][p]
#define OFF_XBF  131072   // 67584  : x bf16 [p][264] (stride 528B)
#define OFF_CAND 198656   // 24576  : u16 cand[128][8][CAPS]
#define OFF_EES  223232   // 4096   : code norms
#define OFF_KEYS 227328   // 1024   : u64 per-pixel (d,k)
#define OFF_CNT  228352   // 2048   : u16 cnt[128][8]
#define OFF_XX   230400   // 512    : pixel norms
#define OFF_FLAG 230912   // 512    : int overflow flag per pixel
#define SMEM_TOTAL 231424

__device__ float g_ee[KNUM];
__device__ float g_embT[KNUM * CDIM];      // [c][k] for gather
__device__ uint2 g_bfrag[65536];           // B fragments: [group128][kstep16][lane32]
__device__ int   g_idx[NPIX];
__device__ float g_losspart[NBLK];

__device__ __forceinline__ uint32_t smem_u32(const void* p) {
    uint32_t a;
    asm("{ .reg .u64 t; cvta.to.shared.u64 t, %1; cvt.u32.u64 %0, t; }" : "=r"(a) : "l"(p));
    return a;
}
__device__ __forceinline__ unsigned pack_bf16(float lo, float hi) {
    return (unsigned)__bfloat16_as_ushort(__float2bfloat16(lo))
         | ((unsigned)__bfloat16_as_ushort(__float2bfloat16(hi)) << 16);
}
__device__ __forceinline__ void ldmA(unsigned a[4], uint32_t addr) {
    asm volatile("ldmatrix.sync.aligned.m8n8.x4.shared.b16 {%0,%1,%2,%3}, [%4];"
                 : "=r"(a[0]), "=r"(a[1]), "=r"(a[2]), "=r"(a[3]) : "r"(addr));
}
__device__ __forceinline__ void mma16816(float d[4], const unsigned a[4], uint2 b) {
    asm("mma.sync.aligned.m16n8k16.row.col.f32.bf16.bf16.f32 "
        "{%0,%1,%2,%3},{%4,%5,%6,%7},{%8,%9},{%0,%1,%2,%3};"
        : "+f"(d[0]), "+f"(d[1]), "+f"(d[2]), "+f"(d[3])
        : "r"(a[0]), "r"(a[1]), "r"(a[2]), "r"(a[3]), "r"(b.x), "r"(b.y));
}

// prep: embT transpose, code norms, B fragments in exact mma register layout
__global__ void prep_kernel(const float* __restrict__ emb) {
    int t = blockIdx.x * 256 + threadIdx.x;            // 262144 threads
    { int c = t >> 10, k = t & 1023; g_embT[t] = emb[k * CDIM + c]; }
    if (t < 65536) {                                   // 128 groups x 16 ksteps x 32 lanes
        int g = t >> 9, rem = t & 511;
        int ks = rem >> 5, lane = rem & 31;
        int n = g * 8 + (lane >> 2);                   // code index (B column)
        int k0 = ks * 16 + (lane & 3) * 2;             // k rows (lane%4)*2 (+8 for .y)
        const float* e = emb + (size_t)n * CDIM;
        uint2 v;
        v.x = pack_bf16(e[k0], e[k0 + 1]);
        v.y = pack_bf16(e[k0 + 8], e[k0 + 9]);
        g_bfrag[(size_t)((g * 16 + ks) * 32 + lane)] = v;
    }
    if (t < KNUM) {
        const float* e = emb + (size_t)t * CDIM;
        float s = 0.f;
        for (int c = 0; c < CDIM; ++c) s = __fadd_rn(s, __fmul_rn(e[c], e[c]));
        g_ee[t] = s;
    }
}

__global__ __launch_bounds__(256, 1)
void vq_mma(const float* __restrict__ x, const float* __restrict__ emb) {
    extern __shared__ char sm[];
    uint32_t sb = smem_u32(sm);
    float* xs  = (float*)(sm + OFF_XS);
    unsigned* xbf = (unsigned*)(sm + OFF_XBF);
    unsigned short* cand = (unsigned short*)(sm + OFF_CAND);
    float* ees = (float*)(sm + OFF_EES);
    unsigned long long* keys = (unsigned long long*)(sm + OFF_KEYS);
    unsigned short* cntS = (unsigned short*)(sm + OFF_CNT);
    float* xxs = (float*)(sm + OFF_XX);
    int* flags = (int*)(sm + OFF_FLAG);

    const int tid = threadIdx.x;
    const int lane = tid & 31, wid = tid >> 5;
    const int wm = wid & 3, wn = wid >> 2;     // 4 M-warps x 2 N-warps
    const int p0 = blockIdx.x * PXB;
    const float* xb = x + ((size_t)(p0 >> 12) * CDIM) * 4096 + (p0 & 4095);

    // stage x fp32 [c][p], coalesced
    for (int v = tid; v < (CDIM * PXB) / 4; v += 256) {
        int c = v >> 5, j = (v & 31) << 2;
        *(float4*)(xs + c * PXB + j) = *(const float4*)(xb + (size_t)c * 4096 + j);
    }
    for (int v = tid; v < KNUM; v += 256) ees[v] = g_ee[v];
    if (tid < PXB) { keys[tid] = 0xFFFFFFFFFFFFFFFFull; flags[tid] = 0; }
    __syncthreads();

    // per-pixel ||x||^2 (round-1 exact chain) + bf16 pack into xbf[p] (stride 132 u32)
    if (tid < PXB) {
        int p = tid;
        float s = 0.f;
        unsigned* xrow = xbf + p * 132;
        for (int c = 0; c < CDIM; c += 2) {
            float v0 = xs[c * PXB + p], v1 = xs[(c + 1) * PXB + p];
            s = __fadd_rn(s, __fmul_rn(v0, v0));
            s = __fadd_rn(s, __fmul_rn(v1, v1));
            xrow[c >> 1] = pack_bf16(v0, v1);
        }
        xxs[p] = s;
    }
    __syncthreads();

    // per-lane pixel slots: i = mf*2 + h ; px = wm*32 + 8*i + lane/4
    const int prow = lane >> 2;
    int px[4]; float xxp[4], mrun[4]; int cnt[4];
    #pragma unroll
    for (int i = 0; i < 4; ++i) {
        px[i] = wm * 32 + 8 * i + prow;
        xxp[i] = xxs[px[i]];
        mrun[i] = 3.0e38f;
        cnt[i] = 0;
    }
    const int subl = wn * 4 + (lane & 3);     // sub-slot (fixes the wn collision)

    const int rowA = wm * 32 + (lane & 15);
    const uint32_t adA0 = sb + OFF_XBF + rowA * 528 + (lane >> 4) * 16;
    const uint32_t adA1 = adA0 + 16 * 528;

    for (int ch = 0; ch < 8; ++ch) {
        float acc[16][4];
        #pragma unroll
        for (int f = 0; f < 16; ++f) { acc[f][0]=0.f; acc[f][1]=0.f; acc[f][2]=0.f; acc[f][3]=0.f; }

        const int gbase = ch * 16 + wn * 8;
        #pragma unroll 2
        for (int ks = 0; ks < 16; ++ks) {
            unsigned a0[4], a1[4];
            ldmA(a0, adA0 + ks * 32);
            ldmA(a1, adA1 + ks * 32);
            #pragma unroll
            for (int nf = 0; nf < 8; ++nf) {
                uint2 b = __ldg(&g_bfrag[((gbase + nf) * 16 + ks) * 32 + lane]);
                mma16816(acc[nf], a0, b);
                mma16816(acc[8 + nf], a1, b);
            }
        }

        // ---- pass A: convert dots -> approx distances in place, track chunk min
        float cmin[4] = {3.0e38f, 3.0e38f, 3.0e38f, 3.0e38f};
        #pragma unroll
        for (int mf = 0; mf < 2; ++mf) {
            #pragma unroll
            for (int nf = 0; nf < 8; ++nf) {
                float* d = acc[mf * 8 + nf];
                int c0 = ch * 128 + wn * 64 + nf * 8 + ((lane & 3) << 1);
                float e0 = ees[c0], e1 = ees[c0 + 1];
                #pragma unroll
                for (int h = 0; h < 2; ++h) {
                    int i = mf * 2 + h;
                    float dd0 = __fmaf_rn(-2.f, d[h * 2 + 0], __fadd_rn(xxp[i], e0));
                    float dd1 = __fmaf_rn(-2.f, d[h * 2 + 1], __fadd_rn(xxp[i], e1));
                    d[h * 2 + 0] = dd0; d[h * 2 + 1] = dd1;
                    cmin[i] = fminf(cmin[i], fminf(dd0, dd1));
                }
            }
        }
        #pragma unroll
        for (int i = 0; i < 4; ++i) {
            float m = cmin[i];
            m = fminf(m, __shfl_xor_sync(0xffffffffu, m, 1));
            m = fminf(m, __shfl_xor_sync(0xffffffffu, m, 2));
            mrun[i] = fminf(mrun[i], m);
        }
        // ---- pass B: record candidates under tightened threshold
        #pragma unroll
        for (int mf = 0; mf < 2; ++mf) {
            #pragma unroll
            for (int nf = 0; nf < 8; ++nf) {
                const float* d = acc[mf * 8 + nf];
                int c0 = ch * 128 + wn * 64 + nf * 8 + ((lane & 3) << 1);
                #pragma unroll
                for (int h = 0; h < 2; ++h) {
                    int i = mf * 2 + h;
                    float thr = mrun[i] + DELTA;
                    if (d[h * 2 + 0] < thr) {
                        if (cnt[i] < CAPS)
                            cand[(px[i] * 8 + subl) * CAPS + cnt[i]] = (unsigned short)c0;
                        ++cnt[i];
                    }
                    if (d[h * 2 + 1] < thr) {
                        if (cnt[i] < CAPS)
                            cand[(px[i] * 8 + subl) * CAPS + cnt[i]] = (unsigned short)(c0 + 1);
                        ++cnt[i];
                    }
                }
            }
        }
    }

    #pragma unroll
    for (int i = 0; i < 4; ++i) {
        cntS[px[i] * 8 + subl] = (unsigned short)(cnt[i] < CAPS ? cnt[i] : CAPS);
        if (cnt[i] > CAPS) flags[px[i]] = 1;   // overflow -> exhaustive fallback
    }
    __syncthreads();

    // exact fp32 rescue: identical chain/formula to the passing round-1 kernel
    for (int s = tid; s < PXB * 8 * CAPS; s += 256) {
        int p = s / (8 * CAPS);
        int r = s - p * (8 * CAPS);
        int sub = r / CAPS, j = r - sub * CAPS;
        if (j < (int)cntS[p * 8 + sub]) {
            int k = cand[(p * 8 + sub) * CAPS + j];
            const float4* e4 = (const float4*)(emb + (size_t)k * CDIM);
            float dot = 0.f;
            #pragma unroll 16
            for (int c4 = 0; c4 < 64; ++c4) {
                float4 ev = __ldg(e4 + c4);
                int c = c4 * 4;
                dot = __fmaf_rn(xs[c * PXB + p], ev.x, dot);
                dot = __fmaf_rn(xs[(c + 1) * PXB + p], ev.y, dot);
                dot = __fmaf_rn(xs[(c + 2) * PXB + p], ev.z, dot);
                dot = __fmaf_rn(xs[(c + 3) * PXB + p], ev.w, dot);
            }
            float t = __fadd_rn(xxs[p], ees[k]);
            float d = __fmaf_rn(-2.f, dot, t);
            unsigned long long key = ((unsigned long long)__float_as_uint(d) << 32) | (unsigned)k;
            atomicMin(&keys[p], key);
        }
    }
    // exhaustive fallback for overflowed pixels (rare; unconditional correctness)
    for (int p = 0; p < PXB; ++p) {
        if (flags[p] == 0) continue;
        for (int k = tid; k < KNUM; k += 256) {
            const float4* e4 = (const float4*)(emb + (size_t)k * CDIM);
            float dot = 0.f;
            #pragma unroll 16
            for (int c4 = 0; c4 < 64; ++c4) {
                float4 ev = __ldg(e4 + c4);
                int c = c4 * 4;
                dot = __fmaf_rn(xs[c * PXB + p], ev.x, dot);
                dot = __fmaf_rn(xs[(c + 1) * PXB + p], ev.y, dot);
                dot = __fmaf_rn(xs[(c + 2) * PXB + p], ev.z, dot);
                dot = __fmaf_rn(xs[(c + 3) * PXB + p], ev.w, dot);
            }
            float t = __fadd_rn(xxs[p], ees[k]);
            float d = __fmaf_rn(-2.f, dot, t);
            unsigned long long key = ((unsigned long long)__float_as_uint(d) << 32) | (unsigned)k;
            atomicMin(&keys[p], key);
        }
    }
    __syncthreads();

    if (tid < PXB) {
        unsigned long long key = keys[tid];
        g_idx[p0 + tid] = (int)(unsigned)(key & 0xffffffffu);
        xxs[tid] = __uint_as_float((unsigned)(key >> 32));  // d_min for loss
    }
    __syncthreads();
    for (int s = 64; s > 0; s >>= 1) {
        if (tid < s) xxs[tid] += xxs[tid + s];
        __syncthreads();
    }
    if (tid == 0) g_losspart[blockIdx.x] = xxs[0];
}

// x_q_out in [B,C,H,W] layout (straight-through value == emb[idx])
__global__ void gather_kernel(float* __restrict__ out, int out_size) {
    int t = blockIdx.x * blockDim.x + threadIdx.x;
    int o = t << 2;
    int bq = o >> 20, r = o & 1048575, c = r >> 12, hw = r & 4095;
    int n = (bq << 12) + hw;
    const float* row = g_embT + c * KNUM;
    float4 v;
    v.x = row[g_idx[n + 0]];
    v.y = row[g_idx[n + 1]];
    v.z = row[g_idx[n + 2]];
    v.w = row[g_idx[n + 3]];
    if (o + 3 < out_size) *(float4*)(out + o) = v;
}

__global__ void tail_kernel(float* __restrict__ out, int out_size) {
    int n = blockIdx.x * blockDim.x + threadIdx.x;
    if (n < NPIX) {
        int o = XQ_ELEMS + n;
        if (o < out_size) out[o] = (float)g_idx[n];
    }
    if (blockIdx.x == 0) {
        __shared__ float red[256];
        float s = 0.f;
        for (int i = threadIdx.x; i < NBLK; i += 256) s += g_losspart[i];
        red[threadIdx.x] = s;
        __syncthreads();
        for (int st = 128; st > 0; st >>= 1) {
            if (threadIdx.x < st) red[threadIdx.x] += red[threadIdx.x + st];
            __syncthreads();
        }
        if (threadIdx.x == 0) {
            int o = XQ_ELEMS + NPIX;
            if (o < out_size) out[o] = red[0] * (1.25f / 33554432.f);
        }
    }
}

extern "C" void kernel_launch(void* const* d_in, const int* in_sizes, int n_in,
                              void* d_out, int out_size) {
    const float* x   = (const float*)d_in[0];
    const float* emb = (const float*)d_in[1];
    float* out = (float*)d_out;

    cudaFuncSetAttribute(vq_mma, cudaFuncAttributeMaxDynamicSharedMemorySize, SMEM_TOTAL);

    prep_kernel<<<1024, 256>>>(emb);
    vq_mma<<<NBLK, 256, SMEM_TOTAL>>>(x, emb);
    gather_kernel<<<XQ_ELEMS / 4 / 256, 256>>>(out, out_size);
    tail_kernel<<<(NPIX + 255) / 256, 256>>>(out, out_size);
}

// round 9
// speedup vs baseline: 1.2296x; 1.0031x over previous
#include <cuda_runtime.h>
#include <cuda_bf16.h>
#include <cstdint>

#define CDIM 256
#define KNUM 1024
#define NPIX 131072
#define PXB  128
#define CAPS 12
#define DELTA 0.004f
#define XQ_ELEMS 33554432
#define NBLK (NPIX / PXB)

// smem byte offsets (total 231424, same as the accepted round-7 size)
#define OFF_XBF  0        // 67584  : x bf16 [p][132 u32] (stride 528B)
#define OFF_B    67584    // 131072 : B fragment chunks, 2 x 64KB double buffer
#define OFF_CAND 198656   // 24576  : u16 cand[128][8][CAPS]
#define OFF_EES  223232   // 4096   : code norms
#define OFF_KEYS 227328   // 1024   : u64 per-pixel (d,k)
#define OFF_CNT  228352   // 2048   : u16 cnt[128][8]
#define OFF_XX   230400   // 512    : pixel norms
#define OFF_FLAG 230912   // 512    : overflow flag per pixel
#define SMEM_TOTAL 231424

__device__ float g_ee[KNUM];
__device__ float g_embT[KNUM * CDIM];              // [c][k] for gather
__device__ __align__(16) uint2 g_bfrag[65536];     // [chunk8][g16][ks16][lane32]
__device__ int   g_idx[NPIX];
__device__ float g_losspart[NBLK];

__device__ __forceinline__ uint32_t smem_u32(const void* p) {
    uint32_t a;
    asm("{ .reg .u64 t; cvta.to.shared.u64 t, %1; cvt.u32.u64 %0, t; }" : "=r"(a) : "l"(p));
    return a;
}
__device__ __forceinline__ unsigned pack_bf16(float lo, float hi) {
    return (unsigned)__bfloat16_as_ushort(__float2bfloat16(lo))
         | ((unsigned)__bfloat16_as_ushort(__float2bfloat16(hi)) << 16);
}
__device__ __forceinline__ void ldmA(unsigned a[4], uint32_t addr) {
    asm volatile("ldmatrix.sync.aligned.m8n8.x4.shared.b16 {%0,%1,%2,%3}, [%4];"
                 : "=r"(a[0]), "=r"(a[1]), "=r"(a[2]), "=r"(a[3]) : "r"(addr));
}
__device__ __forceinline__ void mma16816(float d[4], const unsigned a[4], uint2 b) {
    asm("mma.sync.aligned.m16n8k16.row.col.f32.bf16.bf16.f32 "
        "{%0,%1,%2,%3},{%4,%5,%6,%7},{%8,%9},{%0,%1,%2,%3};"
        : "+f"(d[0]), "+f"(d[1]), "+f"(d[2]), "+f"(d[3])
        : "r"(a[0]), "r"(a[1]), "r"(a[2]), "r"(a[3]), "r"(b.x), "r"(b.y));
}
#define CP_ASYNC16(dst, src) asm volatile("cp.async.cg.shared.global [%0], [%1], 16;" :: "r"((uint32_t)(dst)), "l"(src) : "memory")
#define CP_COMMIT()  asm volatile("cp.async.commit_group;" ::: "memory")
#define CP_WAIT(n)   asm volatile("cp.async.wait_group %0;" :: "n"(n) : "memory")

// prep: embT transpose, code norms, B fragments in exact mma register layout
__global__ void prep_kernel(const float* __restrict__ emb) {
    int t = blockIdx.x * 256 + threadIdx.x;            // 262144 threads
    { int c = t >> 10, k = t & 1023; g_embT[t] = emb[k * CDIM + c]; }
    if (t < 65536) {                                   // 128 groups x 16 ksteps x 32 lanes
        int g = t >> 9, rem = t & 511;
        int ks = rem >> 5, lane = rem & 31;
        int n = g * 8 + (lane >> 2);
        int k0 = ks * 16 + (lane & 3) * 2;
        const float* e = emb + (size_t)n * CDIM;
        uint2 v;
        v.x = pack_bf16(e[k0], e[k0 + 1]);
        v.y = pack_bf16(e[k0 + 8], e[k0 + 9]);
        g_bfrag[(size_t)((g * 16 + ks) * 32 + lane)] = v;
    }
    if (t < KNUM) {
        const float* e = emb + (size_t)t * CDIM;
        float s = 0.f;
        for (int c = 0; c < CDIM; ++c) s = __fadd_rn(s, __fmul_rn(e[c], e[c]));
        g_ee[t] = s;
    }
}

__global__ __launch_bounds__(256, 1)
void vq_mma(const float* __restrict__ x, const float* __restrict__ emb) {
    extern __shared__ char sm[];
    uint32_t sb = smem_u32(sm);
    unsigned* xbf = (unsigned*)(sm + OFF_XBF);
    unsigned short* cand = (unsigned short*)(sm + OFF_CAND);
    float* ees = (float*)(sm + OFF_EES);
    unsigned long long* keys = (unsigned long long*)(sm + OFF_KEYS);
    unsigned short* cntS = (unsigned short*)(sm + OFF_CNT);
    float* xxs = (float*)(sm + OFF_XX);
    int* flags = (int*)(sm + OFF_FLAG);

    const int tid = threadIdx.x;
    const int lane = tid & 31, wid = tid >> 5;
    const int wm = wid & 3, wn = wid >> 2;     // 4 M-warps x 2 N-warps
    const int p0 = blockIdx.x * PXB;
    const float* xb = x + ((size_t)(p0 >> 12) * CDIM) * 4096 + (p0 & 4095);

    // kick off async copy of B chunk 0 into buffer 0
    {
        const char* src = (const char*)g_bfrag;
        for (int t = tid; t < 4096; t += 256)
            CP_ASYNC16(sb + OFF_B + t * 16, src + (size_t)t * 16);
        CP_COMMIT();
    }

    for (int v = tid; v < KNUM; v += 256) ees[v] = g_ee[v];
    if (tid < PXB) { keys[tid] = 0xFFFFFFFFFFFFFFFFull; flags[tid] = 0; }

    // per-pixel ||x||^2 (round-1 exact chain, coalesced gmem reads) + bf16 pack
    if (tid < PXB) {
        int p = tid;
        float s = 0.f;
        unsigned* xrow = xbf + p * 132;
        for (int c = 0; c < CDIM; c += 2) {
            float v0 = __ldg(xb + (size_t)c * 4096 + p);
            float v1 = __ldg(xb + (size_t)(c + 1) * 4096 + p);
            s = __fadd_rn(s, __fmul_rn(v0, v0));
            s = __fadd_rn(s, __fmul_rn(v1, v1));
            xrow[c >> 1] = pack_bf16(v0, v1);
        }
        xxs[p] = s;
    }
    __syncthreads();

    // per-lane pixel slots: i = mf*2 + h ; px = wm*32 + 8*i + lane/4
    const int prow = lane >> 2;
    int px[4]; float xxp[4], mrun[4]; int cnt[4];
    #pragma unroll
    for (int i = 0; i < 4; ++i) {
        px[i] = wm * 32 + 8 * i + prow;
        xxp[i] = xxs[px[i]];
        mrun[i] = 3.0e38f;
        cnt[i] = 0;
    }
    const int subl = wn * 4 + (lane & 3);

    const int rowA = wm * 32 + (lane & 15);
    const uint32_t adA0 = sb + OFF_XBF + rowA * 528 + (lane >> 4) * 16;
    const uint32_t adA1 = adA0 + 16 * 528;
    // B smem read base for this warp's lane (wn*8 groups offset folded per nf)
    const uint32_t bbase = sb + OFF_B + ((wn * 8) * 16 + 0) * 256 + lane * 8;

    for (int ch = 0; ch < 8; ++ch) {
        // prefetch next chunk; wait for current
        if (ch < 7) {
            const char* src = (const char*)g_bfrag + (size_t)(ch + 1) * 65536;
            uint32_t dstb = sb + OFF_B + (uint32_t)((ch + 1) & 1) * 65536u;
            for (int t = tid; t < 4096; t += 256)
                CP_ASYNC16(dstb + t * 16, src + (size_t)t * 16);
            CP_COMMIT();
            CP_WAIT(1);
        } else {
            CP_WAIT(0);
        }
        __syncthreads();

        float acc[16][4];
        #pragma unroll
        for (int f = 0; f < 16; ++f) { acc[f][0]=0.f; acc[f][1]=0.f; acc[f][2]=0.f; acc[f][3]=0.f; }

        const uint32_t bch = bbase + (uint32_t)(ch & 1) * 65536u;
        #pragma unroll 2
        for (int ks = 0; ks < 16; ++ks) {
            unsigned a0[4], a1[4];
            ldmA(a0, adA0 + ks * 32);
            ldmA(a1, adA1 + ks * 32);
            #pragma unroll
            for (int nf = 0; nf < 8; ++nf) {
                uint2 b = *(const uint2*)(sm + (bch - sb) + (uint32_t)(nf * 16 + ks) * 256u);
                mma16816(acc[nf], a0, b);
                mma16816(acc[8 + nf], a1, b);
            }
        }

        // pass A: dots -> distances in place, chunk min
        float cmin[4] = {3.0e38f, 3.0e38f, 3.0e38f, 3.0e38f};
        #pragma unroll
        for (int mf = 0; mf < 2; ++mf) {
            #pragma unroll
            for (int nf = 0; nf < 8; ++nf) {
                float* d = acc[mf * 8 + nf];
                int c0 = ch * 128 + wn * 64 + nf * 8 + ((lane & 3) << 1);
                float e0 = ees[c0], e1 = ees[c0 + 1];
                #pragma unroll
                for (int h = 0; h < 2; ++h) {
                    int i = mf * 2 + h;
                    float dd0 = __fmaf_rn(-2.f, d[h * 2 + 0], __fadd_rn(xxp[i], e0));
                    float dd1 = __fmaf_rn(-2.f, d[h * 2 + 1], __fadd_rn(xxp[i], e1));
                    d[h * 2 + 0] = dd0; d[h * 2 + 1] = dd1;
                    cmin[i] = fminf(cmin[i], fminf(dd0, dd1));
                }
            }
        }
        #pragma unroll
        for (int i = 0; i < 4; ++i) {
            float m = cmin[i];
            m = fminf(m, __shfl_xor_sync(0xffffffffu, m, 1));
            m = fminf(m, __shfl_xor_sync(0xffffffffu, m, 2));
            mrun[i] = fminf(mrun[i], m);
        }
        // pass B: record candidates
        #pragma unroll
        for (int mf = 0; mf < 2; ++mf) {
            #pragma unroll
            for (int nf = 0; nf < 8; ++nf) {
                const float* d = acc[mf * 8 + nf];
                int c0 = ch * 128 + wn * 64 + nf * 8 + ((lane & 3) << 1);
                #pragma unroll
                for (int h = 0; h < 2; ++h) {
                    int i = mf * 2 + h;
                    float thr = mrun[i] + DELTA;
                    if (d[h * 2 + 0] < thr) {
                        if (cnt[i] < CAPS)
                            cand[(px[i] * 8 + subl) * CAPS + cnt[i]] = (unsigned short)c0;
                        ++cnt[i];
                    }
                    if (d[h * 2 + 1] < thr) {
                        if (cnt[i] < CAPS)
                            cand[(px[i] * 8 + subl) * CAPS + cnt[i]] = (unsigned short)(c0 + 1);
                        ++cnt[i];
                    }
                }
            }
        }
        __syncthreads();   // buffer (ch&1) free for reuse at ch+2 prefetch
    }

    #pragma unroll
    for (int i = 0; i < 4; ++i) {
        cntS[px[i] * 8 + subl] = (unsigned short)(cnt[i] < CAPS ? cnt[i] : CAPS);
        if (cnt[i] > CAPS) flags[px[i]] = 1;
    }
    __syncthreads();

    // exact fp32 rescue: identical chain/formula to the passing kernels; x from gmem
    for (int s = tid; s < PXB * 8 * CAPS; s += 256) {
        int p = s / (8 * CAPS);
        int r = s - p * (8 * CAPS);
        int sub = r / CAPS, j = r - sub * CAPS;
        if (j < (int)cntS[p * 8 + sub]) {
            int k = cand[(p * 8 + sub) * CAPS + j];
            const float4* e4 = (const float4*)(emb + (size_t)k * CDIM);
            float dot = 0.f;
            #pragma unroll 16
            for (int c4 = 0; c4 < 64; ++c4) {
                float4 ev = __ldg(e4 + c4);
                int c = c4 * 4;
                dot = __fmaf_rn(__ldg(xb + (size_t)c * 4096 + p),       ev.x, dot);
                dot = __fmaf_rn(__ldg(xb + (size_t)(c + 1) * 4096 + p), ev.y, dot);
                dot = __fmaf_rn(__ldg(xb + (size_t)(c + 2) * 4096 + p), ev.z, dot);
                dot = __fmaf_rn(__ldg(xb + (size_t)(c + 3) * 4096 + p), ev.w, dot);
            }
            float t = __fadd_rn(xxs[p], ees[k]);
            float d = __fmaf_rn(-2.f, dot, t);
            unsigned long long key = ((unsigned long long)__float_as_uint(d) << 32) | (unsigned)k;
            atomicMin(&keys[p], key);
        }
    }
    // exhaustive fallback for overflowed pixels (rare)
    for (int p = 0; p < PXB; ++p) {
        if (flags[p] == 0) continue;
        for (int k = tid; k < KNUM; k += 256) {
            const float4* e4 = (const float4*)(emb + (size_t)k * CDIM);
            float dot = 0.f;
            #pragma unroll 16
            for (int c4 = 0; c4 < 64; ++c4) {
                float4 ev = __ldg(e4 + c4);
                int c = c4 * 4;
                dot = __fmaf_rn(__ldg(xb + (size_t)c * 4096 + p),       ev.x, dot);
                dot = __fmaf_rn(__ldg(xb + (size_t)(c + 1) * 4096 + p), ev.y, dot);
                dot = __fmaf_rn(__ldg(xb + (size_t)(c + 2) * 4096 + p), ev.z, dot);
                dot = __fmaf_rn(__ldg(xb + (size_t)(c + 3) * 4096 + p), ev.w, dot);
            }
            float t = __fadd_rn(xxs[p], ees[k]);
            float d = __fmaf_rn(-2.f, dot, t);
            unsigned long long key = ((unsigned long long)__float_as_uint(d) << 32) | (unsigned)k;
            atomicMin(&keys[p], key);
        }
    }
    __syncthreads();

    if (tid < PXB) {
        unsigned long long key = keys[tid];
        g_idx[p0 + tid] = (int)(unsigned)(key & 0xffffffffu);
        xxs[tid] = __uint_as_float((unsigned)(key >> 32));  // d_min for loss
    }
    __syncthreads();
    for (int s = 64; s > 0; s >>= 1) {
        if (tid < s) xxs[tid] += xxs[tid + s];
        __syncthreads();
    }
    if (tid == 0) g_losspart[blockIdx.x] = xxs[0];
}

// x_q_out in [B,C,H,W] layout (straight-through value == emb[idx])
__global__ void gather_kernel(float* __restrict__ out, int out_size) {
    int t = blockIdx.x * blockDim.x + threadIdx.x;
    int o = t << 2;
    int bq = o >> 20, r = o & 1048575, c = r >> 12, hw = r & 4095;
    int n = (bq << 12) + hw;
    const float* row = g_embT + c * KNUM;
    float4 v;
    v.x = row[g_idx[n + 0]];
    v.y = row[g_idx[n + 1]];
    v.z = row[g_idx[n + 2]];
    v.w = row[g_idx[n + 3]];
    if (o + 3 < out_size) *(float4*)(out + o) = v;
}

__global__ void tail_kernel(float* __restrict__ out, int out_size) {
    int n = blockIdx.x * blockDim.x + threadIdx.x;
    if (n < NPIX) {
        int o = XQ_ELEMS + n;
        if (o < out_size) out[o] = (float)g_idx[n];
    }
    if (blockIdx.x == 0) {
        __shared__ float red[256];
        float s = 0.f;
        for (int i = threadIdx.x; i < NBLK; i += 256) s += g_losspart[i];
        red[threadIdx.x] = s;
        __syncthreads();
        for (int st = 128; st > 0; st >>= 1) {
            if (threadIdx.x < st) red[threadIdx.x] += red[threadIdx.x + st];
            __syncthreads();
        }
        if (threadIdx.x == 0) {
            int o = XQ_ELEMS + NPIX;
            if (o < out_size) out[o] = red[0] * (1.25f / 33554432.f);
        }
    }
}

extern "C" void kernel_launch(void* const* d_in, const int* in_sizes, int n_in,
                              void* d_out, int out_size) {
    const float* x   = (const float*)d_in[0];
    const float* emb = (const float*)d_in[1];
    float* out = (float*)d_out;

    cudaFuncSetAttribute(vq_mma, cudaFuncAttributeMaxDynamicSharedMemorySize, SMEM_TOTAL);

    prep_kernel<<<1024, 256>>>(emb);
    vq_mma<<<NBLK, 256, SMEM_TOTAL>>>(x, emb);
    gather_kernel<<<XQ_ELEMS / 4 / 256, 256>>>(out, out_size);
    tail_kernel<<<(NPIX + 255) / 256, 256>>>(out, out_size);
}

// round 10
// speedup vs baseline: 1.3652x; 1.1103x over previous
#include <cuda_runtime.h>
#include <cuda_bf16.h>
#include <cstdint>

#define CDIM 256
#define KNUM 1024
#define NPIX 131072
#define PXB  128
#define CAPS 12
#define DELTA 0.004f
#define XQ_ELEMS 33554432
#define NBLK (NPIX / PXB)

// smem byte offsets
#define OFF_XBF  0        // 67584  : x bf16 [p][132 u32] (stride 528B)
#define OFF_B    67584    // 131072 : B fragment chunks, 2 x 64KB double buffer
#define OFF_CAND 198656   // 24576  : u16 cand[128][8][CAPS]
#define OFF_EES  223232   // 4096   : code norms
#define OFF_KEYS 227328   // 1024   : u64 per-pixel (d,k)
#define OFF_CNT  228352   // 2048   : u16 cnt[128][8]
#define OFF_XX   230400   // 512    : pixel norms
#define OFF_FLAG 230912   // 512    : per-pixel overflow sub-slot bitmask
#define OFF_PMIN 231424   // 512    : per-pixel running min (float bits)
#define SMEM_TOTAL 231936

__device__ float g_ee[KNUM];
__device__ float g_embT[KNUM * CDIM];              // [c][k] for gather
__device__ __align__(16) uint2 g_bfrag[65536];     // [chunk8][g16][ks16][lane32]
__device__ int   g_idx[NPIX];
__device__ float g_losspart[NBLK];

__device__ __forceinline__ uint32_t smem_u32(const void* p) {
    uint32_t a;
    asm("{ .reg .u64 t; cvta.to.shared.u64 t, %1; cvt.u32.u64 %0, t; }" : "=r"(a) : "l"(p));
    return a;
}
__device__ __forceinline__ unsigned pack_bf16(float lo, float hi) {
    return (unsigned)__bfloat16_as_ushort(__float2bfloat16(lo))
         | ((unsigned)__bfloat16_as_ushort(__float2bfloat16(hi)) << 16);
}
__device__ __forceinline__ void ldmA(unsigned a[4], uint32_t addr) {
    asm volatile("ldmatrix.sync.aligned.m8n8.x4.shared.b16 {%0,%1,%2,%3}, [%4];"
                 : "=r"(a[0]), "=r"(a[1]), "=r"(a[2]), "=r"(a[3]) : "r"(addr));
}
__device__ __forceinline__ void mma16816(float d[4], const unsigned a[4], uint2 b) {
    asm("mma.sync.aligned.m16n8k16.row.col.f32.bf16.bf16.f32 "
        "{%0,%1,%2,%3},{%4,%5,%6,%7},{%8,%9},{%0,%1,%2,%3};"
        : "+f"(d[0]), "+f"(d[1]), "+f"(d[2]), "+f"(d[3])
        : "r"(a[0]), "r"(a[1]), "r"(a[2]), "r"(a[3]), "r"(b.x), "r"(b.y));
}
#define CP_ASYNC16(dst, src) asm volatile("cp.async.cg.shared.global [%0], [%1], 16;" :: "r"((uint32_t)(dst)), "l"(src) : "memory")
#define CP_COMMIT()  asm volatile("cp.async.commit_group;" ::: "memory")
#define CP_WAIT(n)   asm volatile("cp.async.wait_group %0;" :: "n"(n) : "memory")

// prep: embT transpose, code norms, B fragments in exact mma register layout
__global__ void prep_kernel(const float* __restrict__ emb) {
    int t = blockIdx.x * 256 + threadIdx.x;            // 262144 threads
    { int c = t >> 10, k = t & 1023; g_embT[t] = emb[k * CDIM + c]; }
    if (t < 65536) {                                   // 128 groups x 16 ksteps x 32 lanes
        int g = t >> 9, rem = t & 511;
        int ks = rem >> 5, lane = rem & 31;
        int n = g * 8 + (lane >> 2);
        int k0 = ks * 16 + (lane & 3) * 2;
        const float* e = emb + (size_t)n * CDIM;
        uint2 v;
        v.x = pack_bf16(e[k0], e[k0 + 1]);
        v.y = pack_bf16(e[k0 + 8], e[k0 + 9]);
        g_bfrag[(size_t)((g * 16 + ks) * 32 + lane)] = v;
    }
    if (t < KNUM) {
        const float* e = emb + (size_t)t * CDIM;
        float s = 0.f;
        for (int c = 0; c < CDIM; ++c) s = __fadd_rn(s, __fmul_rn(e[c], e[c]));
        g_ee[t] = s;
    }
}

__global__ __launch_bounds__(256, 1)
void vq_mma(const float* __restrict__ x, const float* __restrict__ emb) {
    extern __shared__ char sm[];
    uint32_t sb = smem_u32(sm);
    unsigned* xbf = (unsigned*)(sm + OFF_XBF);
    unsigned short* cand = (unsigned short*)(sm + OFF_CAND);
    float* ees = (float*)(sm + OFF_EES);
    unsigned long long* keys = (unsigned long long*)(sm + OFF_KEYS);
    unsigned short* cntS = (unsigned short*)(sm + OFF_CNT);
    float* xxs = (float*)(sm + OFF_XX);
    int* flags = (int*)(sm + OFF_FLAG);
    unsigned* pmin = (unsigned*)(sm + OFF_PMIN);

    const int tid = threadIdx.x;
    const int lane = tid & 31, wid = tid >> 5;
    const int wm = wid & 3, wn = wid >> 2;     // 4 M-warps x 2 N-warps
    const int p0 = blockIdx.x * PXB;
    const float* xb = x + ((size_t)(p0 >> 12) * CDIM) * 4096 + (p0 & 4095);

    // kick off async copy of B chunk 0 into buffer 0
    {
        const char* src = (const char*)g_bfrag;
        for (int t = tid; t < 4096; t += 256)
            CP_ASYNC16(sb + OFF_B + t * 16, src + (size_t)t * 16);
        CP_COMMIT();
    }

    for (int v = tid; v < KNUM; v += 256) ees[v] = g_ee[v];
    if (tid < PXB) {
        keys[tid] = 0xFFFFFFFFFFFFFFFFull;
        flags[tid] = 0;
        pmin[tid] = 0x7f800000u;              // +inf
    }

    // prologue split: threads 0-127 exact ||x||^2 chain; threads 128-255 bf16 pack
    if (tid < PXB) {
        int p = tid;
        float s = 0.f;
        for (int c = 0; c < CDIM; ++c) {
            float v = __ldg(xb + (size_t)c * 4096 + p);
            s = __fadd_rn(s, __fmul_rn(v, v));
        }
        xxs[p] = s;
    } else {
        int p = tid - PXB;
        unsigned* xrow = xbf + p * 132;
        for (int c = 0; c < CDIM; c += 2) {
            float v0 = __ldg(xb + (size_t)c * 4096 + p);
            float v1 = __ldg(xb + (size_t)(c + 1) * 4096 + p);
            xrow[c >> 1] = pack_bf16(v0, v1);
        }
    }
    __syncthreads();

    // per-lane pixel slots: i = mf*2 + h ; px = wm*32 + 8*i + lane/4
    const int prow = lane >> 2;
    int px[4]; float xxp[4], mrun[4]; int cnt[4];
    #pragma unroll
    for (int i = 0; i < 4; ++i) {
        px[i] = wm * 32 + 8 * i + prow;
        xxp[i] = xxs[px[i]];
        mrun[i] = 3.0e38f;
        cnt[i] = 0;
    }
    const int subl = wn * 4 + (lane & 3);

    const int rowA = wm * 32 + (lane & 15);
    const uint32_t adA0 = sb + OFF_XBF + rowA * 528 + (lane >> 4) * 16;
    const uint32_t adA1 = adA0 + 16 * 528;
    const uint32_t bbase = sb + OFF_B + ((wn * 8) * 16) * 256 + lane * 8;

    for (int ch = 0; ch < 8; ++ch) {
        // prefetch next chunk; wait for current
        if (ch < 7) {
            const char* src = (const char*)g_bfrag + (size_t)(ch + 1) * 65536;
            uint32_t dstb = sb + OFF_B + (uint32_t)((ch + 1) & 1) * 65536u;
            for (int t = tid; t < 4096; t += 256)
                CP_ASYNC16(dstb + t * 16, src + (size_t)t * 16);
            CP_COMMIT();
            CP_WAIT(1);
        } else {
            CP_WAIT(0);
        }
        __syncthreads();

        float acc[16][4];
        #pragma unroll
        for (int f = 0; f < 16; ++f) { acc[f][0]=0.f; acc[f][1]=0.f; acc[f][2]=0.f; acc[f][3]=0.f; }

        const uint32_t bch = bbase + (uint32_t)(ch & 1) * 65536u;
        #pragma unroll 2
        for (int ks = 0; ks < 16; ++ks) {
            unsigned a0[4], a1[4];
            ldmA(a0, adA0 + ks * 32);
            ldmA(a1, adA1 + ks * 32);
            #pragma unroll
            for (int nf = 0; nf < 8; ++nf) {
                uint2 b = *(const uint2*)(sm + (bch - sb) + (uint32_t)(nf * 16 + ks) * 256u);
                mma16816(acc[nf], a0, b);
                mma16816(acc[8 + nf], a1, b);
            }
        }

        // pass A: dots -> distances in place, quad-local chunk min
        float cmin[4] = {3.0e38f, 3.0e38f, 3.0e38f, 3.0e38f};
        #pragma unroll
        for (int mf = 0; mf < 2; ++mf) {
            #pragma unroll
            for (int nf = 0; nf < 8; ++nf) {
                float* d = acc[mf * 8 + nf];
                int c0 = ch * 128 + wn * 64 + nf * 8 + ((lane & 3) << 1);
                float e0 = ees[c0], e1 = ees[c0 + 1];
                #pragma unroll
                for (int h = 0; h < 2; ++h) {
                    int i = mf * 2 + h;
                    float dd0 = __fmaf_rn(-2.f, d[h * 2 + 0], __fadd_rn(xxp[i], e0));
                    float dd1 = __fmaf_rn(-2.f, d[h * 2 + 1], __fadd_rn(xxp[i], e1));
                    d[h * 2 + 0] = dd0; d[h * 2 + 1] = dd1;
                    cmin[i] = fminf(cmin[i], fminf(dd0, dd1));
                }
            }
        }
        #pragma unroll
        for (int i = 0; i < 4; ++i) {
            float m = cmin[i];
            m = fminf(m, __shfl_xor_sync(0xffffffffu, m, 1));
            m = fminf(m, __shfl_xor_sync(0xffffffffu, m, 2));
            mrun[i] = fminf(mrun[i], m);
            // publish quad min to the per-pixel shared running min (d > 0 so
            // float-bits ordering == uint ordering; clamp up to 0 for safety)
            if ((lane & 3) == 0)
                atomicMin(&pmin[px[i]], __float_as_uint(fmaxf(mrun[i], 0.f)));
        }
        // pass B: record candidates under cross-warp-tightened threshold
        #pragma unroll
        for (int mf = 0; mf < 2; ++mf) {
            #pragma unroll
            for (int nf = 0; nf < 8; ++nf) {
                const float* d = acc[mf * 8 + nf];
                int c0 = ch * 128 + wn * 64 + nf * 8 + ((lane & 3) << 1);
                #pragma unroll
                for (int h = 0; h < 2; ++h) {
                    int i = mf * 2 + h;
                    float pm = __uint_as_float(pmin[px[i]]);
                    float thr = fminf(mrun[i], pm) + DELTA;
                    if (d[h * 2 + 0] < thr) {
                        if (cnt[i] < CAPS)
                            cand[(px[i] * 8 + subl) * CAPS + cnt[i]] = (unsigned short)c0;
                        ++cnt[i];
                    }
                    if (d[h * 2 + 1] < thr) {
                        if (cnt[i] < CAPS)
                            cand[(px[i] * 8 + subl) * CAPS + cnt[i]] = (unsigned short)(c0 + 1);
                        ++cnt[i];
                    }
                }
            }
        }
        __syncthreads();   // buffer (ch&1) free for reuse at ch+2 prefetch
    }

    #pragma unroll
    for (int i = 0; i < 4; ++i) {
        cntS[px[i] * 8 + subl] = (unsigned short)(cnt[i] < CAPS ? cnt[i] : CAPS);
        if (cnt[i] > CAPS) atomicOr(&flags[px[i]], 1 << subl);   // sub-slot overflow
    }
    __syncthreads();

    // exact fp32 rescue: identical chain/formula to the passing kernels; x from gmem
    for (int s = tid; s < PXB * 8 * CAPS; s += 256) {
        int p = s / (8 * CAPS);
        int r = s - p * (8 * CAPS);
        int sub = r / CAPS, j = r - sub * CAPS;
        if (j < (int)cntS[p * 8 + sub]) {
            int k = cand[(p * 8 + sub) * CAPS + j];
            const float4* e4 = (const float4*)(emb + (size_t)k * CDIM);
            float dot = 0.f;
            #pragma unroll 16
            for (int c4 = 0; c4 < 64; ++c4) {
                float4 ev = __ldg(e4 + c4);
                int c = c4 * 4;
                dot = __fmaf_rn(__ldg(xb + (size_t)c * 4096 + p),       ev.x, dot);
                dot = __fmaf_rn(__ldg(xb + (size_t)(c + 1) * 4096 + p), ev.y, dot);
                dot = __fmaf_rn(__ldg(xb + (size_t)(c + 2) * 4096 + p), ev.z, dot);
                dot = __fmaf_rn(__ldg(xb + (size_t)(c + 3) * 4096 + p), ev.w, dot);
            }
            float t = __fadd_rn(xxs[p], ees[k]);
            float d = __fmaf_rn(-2.f, dot, t);
            unsigned long long key = ((unsigned long long)__float_as_uint(d) << 32) | (unsigned)k;
            atomicMin(&keys[p], key);
        }
    }
    // sub-slot-granular fallback for overflowed slots (rare), warp-parallel:
    // warp handles item (p, sub); 128 codes of that sub-slot spread over lanes.
    for (int item = wid; item < PXB * 8; item += 8) {
        int p = item >> 3, sub = item & 7;
        if (!(flags[p] & (1 << sub))) continue;
        int wn2 = sub >> 2, l2 = sub & 3;
        for (int j = lane; j < 128; j += 32) {
            int chh = j >> 4, nf = (j >> 1) & 7, b = j & 1;
            int k = chh * 128 + wn2 * 64 + nf * 8 + l2 * 2 + b;
            const float4* e4 = (const float4*)(emb + (size_t)k * CDIM);
            float dot = 0.f;
            #pragma unroll 16
            for (int c4 = 0; c4 < 64; ++c4) {
                float4 ev = __ldg(e4 + c4);
                int c = c4 * 4;
                dot = __fmaf_rn(__ldg(xb + (size_t)c * 4096 + p),       ev.x, dot);
                dot = __fmaf_rn(__ldg(xb + (size_t)(c + 1) * 4096 + p), ev.y, dot);
                dot = __fmaf_rn(__ldg(xb + (size_t)(c + 2) * 4096 + p), ev.z, dot);
                dot = __fmaf_rn(__ldg(xb + (size_t)(c + 3) * 4096 + p), ev.w, dot);
            }
            float t = __fadd_rn(xxs[p], ees[k]);
            float d = __fmaf_rn(-2.f, dot, t);
            unsigned long long key = ((unsigned long long)__float_as_uint(d) << 32) | (unsigned)k;
            atomicMin(&keys[p], key);
        }
    }
    __syncthreads();

    if (tid < PXB) {
        unsigned long long key = keys[tid];
        g_idx[p0 + tid] = (int)(unsigned)(key & 0xffffffffu);
        xxs[tid] = __uint_as_float((unsigned)(key >> 32));  // d_min for loss
    }
    __syncthreads();
    for (int s = 64; s > 0; s >>= 1) {
        if (tid < s) xxs[tid] += xxs[tid + s];
        __syncthreads();
    }
    if (tid == 0) g_losspart[blockIdx.x] = xxs[0];
}

// x_q_out in [B,C,H,W] layout (straight-through value == emb[idx])
__global__ void gather_kernel(float* __restrict__ out, int out_size) {
    int t = blockIdx.x * blockDim.x + threadIdx.x;
    int o = t << 2;
    int bq = o >> 20, r = o & 1048575, c = r >> 12, hw = r & 4095;
    int n = (bq << 12) + hw;
    const float* row = g_embT + c * KNUM;
    float4 v;
    v.x = row[g_idx[n + 0]];
    v.y = row[g_idx[n + 1]];
    v.z = row[g_idx[n + 2]];
    v.w = row[g_idx[n + 3]];
    if (o + 3 < out_size) *(float4*)(out + o) = v;
}

__global__ void tail_kernel(float* __restrict__ out, int out_size) {
    int n = blockIdx.x * blockDim.x + threadIdx.x;
    if (n < NPIX) {
        int o = XQ_ELEMS + n;
        if (o < out_size) out[o] = (float)g_idx[n];
    }
    if (blockIdx.x == 0) {
        __shared__ float red[256];
        float s = 0.f;
        for (int i = threadIdx.x; i < NBLK; i += 256) s += g_losspart[i];
        red[threadIdx.x] = s;
        __syncthreads();
        for (int st = 128; st > 0; st >>= 1) {
            if (threadIdx.x < st) red[threadIdx.x] += red[threadIdx.x + st];
            __syncthreads();
        }
        if (threadIdx.x == 0) {
            int o = XQ_ELEMS + NPIX;
            if (o < out_size) out[o] = red[0] * (1.25f / 33554432.f);
        }
    }
}

extern "C" void kernel_launch(void* const* d_in, const int* in_sizes, int n_in,
                              void* d_out, int out_size) {
    const float* x   = (const float*)d_in[0];
    const float* emb = (const float*)d_in[1];
    float* out = (float*)d_out;

    cudaFuncSetAttribute(vq_mma, cudaFuncAttributeMaxDynamicSharedMemorySize, SMEM_TOTAL);

    prep_kernel<<<1024, 256>>>(emb);
    vq_mma<<<NBLK, 256, SMEM_TOTAL>>>(x, emb);
    gather_kernel<<<XQ_ELEMS / 4 / 256, 256>>>(out, out_size);
    tail_kernel<<<(NPIX + 255) / 256, 256>>>(out, out_size);
}